// round 2
// baseline (speedup 1.0000x reference)
#include <cuda_runtime.h>

typedef unsigned long long u64;

#define LOG2E 1.4426950408889634f
#define LN2   0.6931471805599453f
#define B   512
#define TT  1024
#define L   48
#define DSTG 8   // emission ring depth (steps of lookahead)

__device__ float g_fwd[B];
__device__ float g_gold[B];

static __device__ __forceinline__ u64 pk2(float lo, float hi){ u64 r; asm("mov.b64 %0, {%1, %2};" : "=l"(r) : "f"(lo), "f"(hi)); return r; }
static __device__ __forceinline__ void upk2(u64 v, float& lo, float& hi){ asm("mov.b64 {%0, %1}, %2;" : "=f"(lo), "=f"(hi) : "l"(v)); }
static __device__ __forceinline__ u64 fma2(u64 a, u64 b, u64 c){ u64 d; asm("fma.rn.f32x2 %0, %1, %2, %3;" : "=l"(d) : "l"(a), "l"(b), "l"(c)); return d; }
static __device__ __forceinline__ u64 mul2(u64 a, u64 b){ u64 d; asm("mul.rn.f32x2 %0, %1, %2;" : "=l"(d) : "l"(a), "l"(b)); return d; }
static __device__ __forceinline__ u64 add2(u64 a, u64 b){ u64 d; asm("add.rn.f32x2 %0, %1, %2;" : "=l"(d) : "l"(a), "l"(b)); return d; }
static __device__ __forceinline__ float ex2f(float x){ float y; asm("ex2.approx.ftz.f32 %0, %1;" : "=f"(y) : "f"(x)); return y; }
static __device__ __forceinline__ float lg2f(float x){ float y; asm("lg2.approx.ftz.f32 %0, %1;" : "=f"(y) : "f"(x)); return y; }

// ---------------------------------------------------------------------------
// Forward (logZ) kernel: 128 blocks x 128 threads.
// Block owns 4 sequences (2 f32x2 pairs). tid<96: consumers (g=pair, j=label).
// tid>=96: producer warp filling exp(emissions) + mask ring DSTG steps ahead.
// State u kept unnormalized; per-seq log-scale accumulated at renorms.
// ---------------------------------------------------------------------------
__global__ __launch_bounds__(128, 1) void crf_fwd_kernel(
    const float* __restrict__ em, const int* __restrict__ mask,
    const float* __restrict__ trans, const float* __restrict__ startt,
    const float* __restrict__ endt)
{
    __shared__ __align__(16) u64 sh_u[2][2][L];     // ping-pong state, packed pair
    __shared__ __align__(16) u64 sh_E[DSTG][2][L];  // exp(emissions) ring
    __shared__ __align__(16) u64 sh_M[DSTG][2][L];  // mask bits ring (all-ones / 0 per half)
    __shared__ __align__(16) u64 sc[2][L];          // reduce scratch (packed)
    __shared__ float scr2[32];
    __shared__ float sh_scale[4];
    __shared__ float sh_inv[4];
    __shared__ int   sh_flag;

    const int tid = threadIdx.x;
    const int b0  = blockIdx.x * 4;
    const bool isCons = tid < 96;
    const int g = tid / 48;      // pair index for consumers
    const int j = tid % 48;      // label for consumers
    const int lane = tid - 96;   // producer lane

    if (tid == 0) sh_flag = 0;

    u64 et[L];           // exp(T[i][j]) splatted, column j in registers
    float expEnd = 0.f;
    u64 s0pk = 0;

    if (isCons) {
        #pragma unroll
        for (int i = 0; i < L; i++) {
            float tv = trans[i * L + j];
            float e  = ex2f(tv * LOG2E);
            et[i] = pk2(e, e);
        }
        expEnd = ex2f(endt[j] * LOG2E);
        int ba = b0 + 2 * g, bb = ba + 1;
        float sv = startt[j];
        float sa = sv + em[(size_t)(ba * TT) * L + j];
        float sb = sv + em[(size_t)(bb * TT) * L + j];
        s0pk = pk2(sa, sb);
        sc[g][j] = s0pk;
    } else {
        // producer prefill: steps 1..DSTG-1
        for (int tp = 1; tp < DSTG; ++tp) {
            #pragma unroll
            for (int r = 0; r < 6; r++) {
                int s = lane + 32 * r;
                int seq = s / 48; int jj = s - seq * 48;
                int b = b0 + seq;
                float e = em[((size_t)(b * TT) + tp) * L + jj];
                ((float*)&sh_E[tp][seq >> 1][jj])[seq & 1] = ex2f(e * LOG2E);
                ((unsigned*)&sh_M[tp][seq >> 1][jj])[seq & 1] = mask[b * TT + tp] ? 0xFFFFFFFFu : 0u;
            }
        }
    }
    __syncthreads();

    // init: per-seq max of s0 -> scale; u0 = exp(s0 - scale)
    if (tid < 32) {
        int seq = tid >> 3, k = tid & 7;
        const float* base = ((const float*)&sc[seq >> 1][0]) + (seq & 1);
        float m = -3.4e38f;
        #pragma unroll
        for (int jj = k; jj < L; jj += 8) m = fmaxf(m, base[jj * 2]);
        scr2[tid] = m;
    }
    __syncthreads();
    if (tid < 4) {
        float m = -3.4e38f;
        #pragma unroll
        for (int q = 0; q < 8; q++) m = fmaxf(m, scr2[tid * 8 + q]);
        sh_scale[tid] = m;
    }
    __syncthreads();

    u64 res = 0;
    if (isCons) {
        float sa, sb; upk2(s0pk, sa, sb);
        float ua = ex2f((sa - sh_scale[2 * g])     * LOG2E);
        float ub = ex2f((sb - sh_scale[2 * g + 1]) * LOG2E);
        res = pk2(ua, ub);
        sh_u[0][g][j] = res;
    }
    __syncthreads();

    for (int t = 1; t < TT; ++t) {
        int doR = sh_flag | ((t & 63) == 0);
        int rb = (t - 1) & 1, wb = t & 1;

        if (doR) {  // renormalize: scale by 1/max(u), accumulate log(max)
            if (tid < 32) {
                int seq = tid >> 3, k = tid & 7;
                const float* base = ((const float*)&sh_u[rb][seq >> 1][0]) + (seq & 1);
                float m = 0.f;
                #pragma unroll
                for (int jj = k; jj < L; jj += 8) m = fmaxf(m, base[jj * 2]);
                scr2[tid] = m;
            }
            __syncthreads();
            if (tid < 4) {
                float m = 0.f;
                #pragma unroll
                for (int q = 0; q < 8; q++) m = fmaxf(m, scr2[tid * 8 + q]);
                m = fmaxf(m, 1e-35f);
                sh_scale[tid] += lg2f(m) * LN2;
                sh_inv[tid] = 1.0f / m;
                if (tid == 0) sh_flag = 0;
            }
            __syncthreads();
        }

        int slot = t & (DSTG - 1);
        if (isCons) {
            const ulonglong2* up = reinterpret_cast<const ulonglong2*>(&sh_u[rb][g][0]);
            u64 a0 = 0, a1 = 0, a2 = 0, a3 = 0;
            #pragma unroll
            for (int q = 0; q < 12; q++) {
                ulonglong2 v0 = up[2 * q];
                ulonglong2 v1 = up[2 * q + 1];
                a0 = fma2(v0.x, et[4 * q + 0], a0);
                a1 = fma2(v0.y, et[4 * q + 1], a1);
                a2 = fma2(v1.x, et[4 * q + 2], a2);
                a3 = fma2(v1.y, et[4 * q + 3], a3);
            }
            u64 dot = add2(add2(a0, a1), add2(a2, a3));
            u64 Ev   = sh_E[slot][g][j];
            u64 mm   = sh_M[slot][g][j];
            u64 uold = sh_u[rb][g][j];
            u64 prod = mul2(dot, Ev);
            u64 sel  = (prod & mm) | (uold & ~mm);   // bitwise exact mask select
            if (doR) {
                // apply this step's renorm factor ONLY on renorm steps
                u64 invPk = pk2(sh_inv[2 * g], sh_inv[2 * g + 1]);
                res = mul2(sel, invPk);
            } else {
                res = sel;
            }
            sh_u[wb][g][j] = res;
            float f0, f1; upk2(res, f0, f1);
            if (fmaxf(f0, f1) > 0x1p80f) sh_flag = 1;  // schedule renorm next step
        } else {
            int tp = t + DSTG - 1;
            if (tp < TT) {
                int sl2 = tp & (DSTG - 1);
                #pragma unroll
                for (int r = 0; r < 6; r++) {
                    int s = lane + 32 * r;
                    int seq = s / 48; int jj = s - seq * 48;
                    int b = b0 + seq;
                    float e = em[((size_t)(b * TT) + tp) * L + jj];
                    ((float*)&sh_E[sl2][seq >> 1][jj])[seq & 1] = ex2f(e * LOG2E);
                    ((unsigned*)&sh_M[sl2][seq >> 1][jj])[seq & 1] = mask[b * TT + tp] ? 0xFFFFFFFFu : 0u;
                }
            }
        }
        __syncthreads();
    }

    // finalize: logZ = log(sum_j u[j]*exp(end[j])) + scale
    if (isCons) sc[g][j] = mul2(res, pk2(expEnd, expEnd));
    __syncthreads();
    if (tid < 32) {
        int seq = tid >> 3, k = tid & 7;
        const float* base = ((const float*)&sc[seq >> 1][0]) + (seq & 1);
        float sm = 0.f;
        #pragma unroll
        for (int jj = k; jj < L; jj += 8) sm += base[jj * 2];
        scr2[tid] = sm;
    }
    __syncthreads();
    if (tid < 4) {
        float sm = 0.f;
        #pragma unroll
        for (int q = 0; q < 8; q++) sm += scr2[tid * 8 + q];
        g_fwd[b0 + tid] = lg2f(sm) * LN2 + sh_scale[tid];
    }
}

// ---------------------------------------------------------------------------
// Gold score kernel: one block per batch element.
// ---------------------------------------------------------------------------
__global__ __launch_bounds__(256, 4) void crf_gold_kernel(
    const float* __restrict__ em, const int* __restrict__ labels,
    const int* __restrict__ mask, const float* __restrict__ trans,
    const float* __restrict__ startt, const float* __restrict__ endt)
{
    __shared__ float red[256];
    __shared__ int   redc[256];
    const int b = blockIdx.x;
    const int tid = threadIdx.x;

    float acc = 0.f;
    int cnt = 0;
    for (int t = tid; t < TT; t += 256) {
        int l = labels[b * TT + t];
        int m = mask[b * TT + t];
        cnt += m;
        float e = em[((size_t)(b * TT) + t) * L + l];
        if (t == 0) {
            acc += startt[l] + e;
        } else {
            int lp = labels[b * TT + t - 1];
            acc += (e + trans[l * L + lp]) * (float)m;
        }
    }
    red[tid] = acc; redc[tid] = cnt;
    __syncthreads();
    for (int s = 128; s > 0; s >>= 1) {
        if (tid < s) { red[tid] += red[tid + s]; redc[tid] += redc[tid + s]; }
        __syncthreads();
    }
    if (tid == 0) {
        int len = redc[0] - 1;
        int last = labels[b * TT + len];
        g_gold[b] = red[0] + endt[last];
    }
}

// ---------------------------------------------------------------------------
// Final reduction: mean(fwd - gold)
// ---------------------------------------------------------------------------
__global__ __launch_bounds__(512, 1) void crf_final_kernel(float* __restrict__ out)
{
    __shared__ float red[512];
    int tid = threadIdx.x;
    red[tid] = g_fwd[tid] - g_gold[tid];
    __syncthreads();
    for (int s = 256; s > 0; s >>= 1) {
        if (tid < s) red[tid] += red[tid + s];
        __syncthreads();
    }
    if (tid == 0) out[0] = red[0] * (1.0f / (float)B);
}

extern "C" void kernel_launch(void* const* d_in, const int* in_sizes, int n_in,
                              void* d_out, int out_size)
{
    const float* em     = (const float*)d_in[0];
    const int*   labels = (const int*)  d_in[1];
    const int*   mask   = (const int*)  d_in[2];
    const float* trans  = (const float*)d_in[3];
    const float* startt = (const float*)d_in[4];
    const float* endt   = (const float*)d_in[5];
    float* out = (float*)d_out;

    crf_fwd_kernel<<<B / 4, 128>>>(em, mask, trans, startt, endt);
    crf_gold_kernel<<<B, 256>>>(em, labels, mask, trans, startt, endt);
    crf_final_kernel<<<1, 512>>>(out);
}

// round 3
// speedup vs baseline: 1.2581x; 1.2581x over previous
#include <cuda_runtime.h>

typedef unsigned long long u64;

#define LOG2E 1.4426950408889634f
#define LN2   0.6931471805599453f
#define B    512
#define TT   1024
#define L    48
#define DSTG 16   // emission ring slots
#define NRND 1024 // barrier rounds (t = 1..1024; t==1024 is a dummy round)

__device__ float g_fwd[B];
__device__ float g_gold[B];

static __device__ __forceinline__ u64 pk2(float lo, float hi){ u64 r; asm("mov.b64 %0, {%1, %2};" : "=l"(r) : "f"(lo), "f"(hi)); return r; }
static __device__ __forceinline__ void upk2(u64 v, float& lo, float& hi){ asm("mov.b64 {%0, %1}, %2;" : "=f"(lo), "=f"(hi) : "l"(v)); }
static __device__ __forceinline__ u64 fma2(u64 a, u64 b, u64 c){ u64 d; asm("fma.rn.f32x2 %0, %1, %2, %3;" : "=l"(d) : "l"(a), "l"(b), "l"(c)); return d; }
static __device__ __forceinline__ u64 mul2(u64 a, u64 b){ u64 d; asm("mul.rn.f32x2 %0, %1, %2;" : "=l"(d) : "l"(a), "l"(b)); return d; }
static __device__ __forceinline__ u64 add2(u64 a, u64 b){ u64 d; asm("add.rn.f32x2 %0, %1, %2;" : "=l"(d) : "l"(a), "l"(b)); return d; }
static __device__ __forceinline__ float ex2f(float x){ float y; asm("ex2.approx.ftz.f32 %0, %1;" : "=f"(y) : "f"(x)); return y; }
static __device__ __forceinline__ float lg2f(float x){ float y; asm("lg2.approx.ftz.f32 %0, %1;" : "=f"(y) : "f"(x)); return y; }
static __device__ __forceinline__ float rcpf(float x){ float y; asm("rcp.approx.ftz.f32 %0, %1;" : "=f"(y) : "f"(x)); return y; }

// ---------------------------------------------------------------------------
// Forward (logZ) kernel: 128 blocks x 128 threads.
// Block owns 4 sequences (2 f32x2 pairs). tid<96: consumers (g=pair, j=label).
// tid>=96: producer warp with an 8-stage register LDG pipeline feeding a
// 16-slot smem ring of exp(emissions)+mask. One __syncthreads per step.
// Renorm every 8 steps is computed redundantly per-thread (no reductions).
// ---------------------------------------------------------------------------
__global__ __launch_bounds__(128, 1) void crf_fwd_kernel(
    const float* __restrict__ em, const int* __restrict__ mask,
    const float* __restrict__ trans, const float* __restrict__ startt,
    const float* __restrict__ endt)
{
    __shared__ __align__(16) u64 sh_u[2][2][L];      // ping-pong state (packed pair)
    __shared__ __align__(16) u64 sh_E[DSTG][2][L];   // exp(emissions) ring
    __shared__ unsigned sh_Mv[DSTG][4];              // mask bits ring, per seq
    __shared__ __align__(16) u64 sc[2][L];           // final reduce scratch
    __shared__ float scr2[32];
    __shared__ float sh_scaleOut[4];

    const int tid = threadIdx.x;
    const int b0  = blockIdx.x * 4;
    const bool isCons = tid < 96;
    const int g = tid / 48;        // pair index (consumers)
    const int j = tid % 48;        // label (consumers)
    const int lane = tid - 96;     // producer lane

    if (isCons) {
        // ------------------------- CONSUMER -------------------------
        u64 et[L];                 // exp(T[i][j]) splatted
        #pragma unroll
        for (int i = 0; i < L; i++) {
            float e = ex2f(trans[i * L + j] * LOG2E);
            et[i] = pk2(e, e);
        }
        const float expEnd = ex2f(endt[j] * LOG2E);
        const int ba = b0 + 2 * g, bb = ba + 1;
        const float sv = startt[j];
        float sa = sv + em[(size_t)(ba * TT) * L + j];
        float sb = sv + em[(size_t)(bb * TT) * L + j];
        u64 res = pk2(ex2f(sa * LOG2E), ex2f(sb * LOG2E));
        float sAlo = 0.f, sAhi = 0.f;   // accumulated log2 scale per seq
        sh_u[0][g][j] = res;

        __syncthreads();   // matches producer prologue barrier

        for (int t = 1; t <= NRND; ++t) {
            if (t < TT) {
                const int rb = (t - 1) & 1, wb = t & 1;
                const ulonglong2* up = reinterpret_cast<const ulonglong2*>(&sh_u[rb][g][0]);
                u64 a0 = 0, a1 = 0, a2 = 0, a3 = 0;
                #pragma unroll
                for (int q = 0; q < 12; q++) {
                    ulonglong2 v0 = up[2 * q];
                    ulonglong2 v1 = up[2 * q + 1];
                    a0 = fma2(v0.x, et[4 * q + 0], a0);
                    a1 = fma2(v0.y, et[4 * q + 1], a1);
                    a2 = fma2(v1.x, et[4 * q + 2], a2);
                    a3 = fma2(v1.y, et[4 * q + 3], a3);
                }
                u64 dot = add2(add2(a0, a1), add2(a2, a3));
                const int slot = t & (DSTG - 1);
                u64 Ev = sh_E[slot][g][j];
                unsigned mlo = sh_Mv[slot][2 * g];
                unsigned mhi = sh_Mv[slot][2 * g + 1];
                u64 mm = (u64)mlo | ((u64)mhi << 32);
                u64 prod = mul2(dot, Ev);
                u64 sel  = (prod & mm) | (res & ~mm);   // exact masked select

                if ((t & 7) == 0) {
                    // Renorm: per-thread redundant max over u(t-1) (identical
                    // across the group -> uniform scale, no reduction needed).
                    float m0 = 1e-30f, m1 = 1e-30f;
                    #pragma unroll
                    for (int q = 0; q < 12; q++) {
                        ulonglong2 v0 = up[2 * q];
                        ulonglong2 v1 = up[2 * q + 1];
                        float x0, x1;
                        upk2(v0.x, x0, x1); m0 = fmaxf(m0, x0); m1 = fmaxf(m1, x1);
                        upk2(v0.y, x0, x1); m0 = fmaxf(m0, x0); m1 = fmaxf(m1, x1);
                        upk2(v1.x, x0, x1); m0 = fmaxf(m0, x0); m1 = fmaxf(m1, x1);
                        upk2(v1.y, x0, x1); m0 = fmaxf(m0, x0); m1 = fmaxf(m1, x1);
                    }
                    float r0 = rcpf(m0), r1 = rcpf(m1);
                    sAlo += lg2f(m0) + lg2f(r0) * -1.0f - lg2f(r0) * -1.0f; // lg2f(m0)
                    sAhi += lg2f(m1);
                    // credit must match the applied factor: applied = r0,r1
                    // (approx rcp); credit -log2(r) instead of log2(m) for exactness
                    sAlo += -lg2f(r0) - lg2f(m0);   // net: -lg2f(r0)
                    sAhi += -lg2f(r1) - lg2f(m1);
                    sel = mul2(sel, pk2(r0, r1));
                }
                res = sel;
                sh_u[wb][g][j] = res;
            }
            __syncthreads();
        }

        // finalize: store weighted state + per-seq scale
        sc[g][j] = mul2(res, pk2(expEnd, expEnd));
        if (j == 0) { sh_scaleOut[2 * g] = sAlo; sh_scaleOut[2 * g + 1] = sAhi; }
    } else {
        // ------------------------- PRODUCER -------------------------
        // smem ring slots 1..8 filled directly; register stages hold tp=9..16.
        float pbuf[8][6];
        unsigned pm[8];
        const int ml = lane & 3;

        for (int tp = 1; tp <= 8; ++tp) {
            #pragma unroll
            for (int r = 0; r < 6; r++) {
                int s = lane + 32 * r;
                int seq = s / 48, jj = s - seq * 48;
                float e = em[((size_t)((b0 + seq) * TT) + tp) * L + jj];
                ((float*)&sh_E[tp][seq >> 1][jj])[seq & 1] = ex2f(e * LOG2E);
            }
            if (lane < 4) sh_Mv[tp][lane] = mask[(b0 + lane) * TT + tp] ? 0xFFFFFFFFu : 0u;
        }
        #pragma unroll
        for (int i = 1; i <= 8; ++i) {   // stage (i&7) <- tp = i+8
            int st = i & 7;
            int tp = i + 8;
            #pragma unroll
            for (int r = 0; r < 6; r++) {
                int s = lane + 32 * r;
                int seq = s / 48, jj = s - seq * 48;
                pbuf[st][r] = em[((size_t)((b0 + seq) * TT) + tp) * L + jj];
            }
            pm[st] = mask[(b0 + ml) * TT + tp] ? 0xFFFFFFFFu : 0u;
        }

        __syncthreads();   // matches consumer init barrier

        for (int tb = 1; tb <= NRND; tb += 8) {
            #pragma unroll
            for (int k = 0; k < 8; ++k) {
                const int t = tb + k;
                const int st = t & 7;          // static: (1+k)&7
                const int tp = t + 8;          // stage st holds em for tp
                if (tp < TT) {
                    const int slot = tp & (DSTG - 1);
                    #pragma unroll
                    for (int r = 0; r < 6; r++) {
                        int s = lane + 32 * r;
                        int seq = s / 48, jj = s - seq * 48;
                        ((float*)&sh_E[slot][seq >> 1][jj])[seq & 1] = ex2f(pbuf[st][r] * LOG2E);
                    }
                    if (lane < 4) sh_Mv[slot][lane] = pm[st];
                    const int tp2 = t + 16;    // reissue stage for 8 rounds ahead
                    if (tp2 < TT) {
                        #pragma unroll
                        for (int r = 0; r < 6; r++) {
                            int s = lane + 32 * r;
                            int seq = s / 48, jj = s - seq * 48;
                            pbuf[st][r] = em[((size_t)((b0 + seq) * TT) + tp2) * L + jj];
                        }
                        pm[st] = mask[(b0 + ml) * TT + tp2] ? 0xFFFFFFFFu : 0u;
                    }
                }
                __syncthreads();
            }
        }
    }

    // ----------------------- final reduction (all threads) -----------------------
    __syncthreads();
    if (tid < 32) {
        int seq = tid >> 3, k = tid & 7;
        const float* base = ((const float*)&sc[seq >> 1][0]) + (seq & 1);
        float sm = 0.f;
        #pragma unroll
        for (int jj = k; jj < L; jj += 8) sm += base[jj * 2];
        scr2[tid] = sm;
    }
    __syncthreads();
    if (tid < 4) {
        float sm = 0.f;
        #pragma unroll
        for (int q = 0; q < 8; q++) sm += scr2[tid * 8 + q];
        g_fwd[b0 + tid] = (lg2f(sm) + sh_scaleOut[tid]) * LN2;
    }
}

// ---------------------------------------------------------------------------
// Gold score kernel: one block per batch element.
// ---------------------------------------------------------------------------
__global__ __launch_bounds__(256, 4) void crf_gold_kernel(
    const float* __restrict__ em, const int* __restrict__ labels,
    const int* __restrict__ mask, const float* __restrict__ trans,
    const float* __restrict__ startt, const float* __restrict__ endt)
{
    __shared__ float red[256];
    __shared__ int   redc[256];
    const int b = blockIdx.x;
    const int tid = threadIdx.x;

    float acc = 0.f;
    int cnt = 0;
    for (int t = tid; t < TT; t += 256) {
        int l = labels[b * TT + t];
        int m = mask[b * TT + t];
        cnt += m;
        float e = em[((size_t)(b * TT) + t) * L + l];
        if (t == 0) {
            acc += startt[l] + e;
        } else {
            int lp = labels[b * TT + t - 1];
            acc += (e + trans[l * L + lp]) * (float)m;
        }
    }
    red[tid] = acc; redc[tid] = cnt;
    __syncthreads();
    for (int s = 128; s > 0; s >>= 1) {
        if (tid < s) { red[tid] += red[tid + s]; redc[tid] += redc[tid + s]; }
        __syncthreads();
    }
    if (tid == 0) {
        int len = redc[0] - 1;
        int last = labels[b * TT + len];
        g_gold[b] = red[0] + endt[last];
    }
}

// ---------------------------------------------------------------------------
// Final reduction: mean(fwd - gold)
// ---------------------------------------------------------------------------
__global__ __launch_bounds__(512, 1) void crf_final_kernel(float* __restrict__ out)
{
    __shared__ float red[512];
    int tid = threadIdx.x;
    red[tid] = g_fwd[tid] - g_gold[tid];
    __syncthreads();
    for (int s = 256; s > 0; s >>= 1) {
        if (tid < s) red[tid] += red[tid + s];
        __syncthreads();
    }
    if (tid == 0) out[0] = red[0] * (1.0f / (float)B);
}

extern "C" void kernel_launch(void* const* d_in, const int* in_sizes, int n_in,
                              void* d_out, int out_size)
{
    const float* em     = (const float*)d_in[0];
    const int*   labels = (const int*)  d_in[1];
    const int*   mask   = (const int*)  d_in[2];
    const float* trans  = (const float*)d_in[3];
    const float* startt = (const float*)d_in[4];
    const float* endt   = (const float*)d_in[5];
    float* out = (float*)d_out;

    crf_fwd_kernel<<<B / 4, 128>>>(em, mask, trans, startt, endt);
    crf_gold_kernel<<<B, 256>>>(em, labels, mask, trans, startt, endt);
    crf_final_kernel<<<1, 512>>>(out);
}